// round 1
// baseline (speedup 1.0000x reference)
#include <cuda_runtime.h>
#include <math.h>

#define TILE 128

// Global accumulators (no device allocation allowed; __device__ globals are the
// sanctioned scratch). Zeroed by init_counters at the start of every launch so
// the kernel_launch sequence is graph-replay deterministic.
__device__ unsigned long long g_c;
__device__ unsigned long long g_t;

__global__ void init_counters() {
    g_c = 0ull;
    g_t = 0ull;
}

// One block handles one 128x128 tile of the strict upper triangle (pairs i<j).
// blockIdx.x is decoded to (ti, tj) with ti <= tj. Thread t owns row
// i = ti*TILE + t and iterates over the j-tile held in shared memory
// (broadcast reads — conflict-free).
__global__ void __launch_bounds__(128)
pair_kernel(const float* __restrict__ y,
            const float* __restrict__ yh,
            const int*   __restrict__ st,
            int N)
{
    // ---- triangular decode: find r with r(r+1)/2 <= k < (r+1)(r+2)/2 ----
    const int k = blockIdx.x;
    int r = (int)((sqrtf(8.0f * (float)k + 1.0f) - 1.0f) * 0.5f);
    while ((r * (r + 1)) / 2 > k) --r;
    while (((r + 1) * (r + 2)) / 2 <= k) ++r;
    const int ti = k - (r * (r + 1)) / 2;  // column index  (<= r)
    const int tj = r;                      // row index: ti <= tj

    __shared__ float sy[TILE];
    __shared__ float syh[TILE];
    __shared__ int   ss[TILE];

    const int t = threadIdx.x;

    // Load the j-tile (coalesced). Out-of-range -> NaN so every comparison is
    // false and the padded element contributes 0 to both counters.
    {
        const int jg = tj * TILE + t;
        if (jg < N) {
            sy[t]  = y[jg];
            syh[t] = yh[jg];
            ss[t]  = (st[jg] == 1);
        } else {
            sy[t]  = __int_as_float(0x7fc00000);  // NaN
            syh[t] = __int_as_float(0x7fc00000);
            ss[t]  = 0;
        }
    }
    __syncthreads();

    // Per-thread i data.
    float yi, yhi;
    int si;
    {
        const int ig = ti * TILE + t;
        if (ig < N) {
            yi  = y[ig];
            yhi = yh[ig];
            si  = (st[ig] == 1);
        } else {
            yi  = __int_as_float(0x7fc00000);
            yhi = __int_as_float(0x7fc00000);
            si  = 0;
        }
    }

    unsigned int cc = 0, tp = 0;

    if (ti == tj) {
        // Diagonal tile: only local pairs j > i.
        for (int j = t + 1; j < TILE; ++j) {
            const float yj = sy[j], yhj = syh[j];
            const int sj = ss[j];
            const int ge  = (yi  >= yj);
            const int le  = (yi  <= yj);
            const int geh = (yhi >= yhj);
            const int leh = (yhi <= yhj);
            cc += (ge & geh & sj) | (le & leh & si);
            tp += (le & si) | (ge & sj);
        }
    } else {
        // Off-diagonal tile: every (i in ti-tile, j in tj-tile) has i < j.
        #pragma unroll 16
        for (int j = 0; j < TILE; ++j) {
            const float yj = sy[j], yhj = syh[j];
            const int sj = ss[j];
            const int ge  = (yi  >= yj);
            const int le  = (yi  <= yj);
            const int geh = (yhi >= yhj);
            const int leh = (yhi <= yhj);
            cc += (ge & geh & sj) | (le & leh & si);
            tp += (le & si) | (ge & sj);
        }
    }

    // Warp reduce, then one pair of atomics per warp.
    #pragma unroll
    for (int o = 16; o > 0; o >>= 1) {
        cc += __shfl_down_sync(0xffffffffu, cc, o);
        tp += __shfl_down_sync(0xffffffffu, tp, o);
    }
    if ((t & 31) == 0) {
        atomicAdd(&g_c, (unsigned long long)cc);
        atomicAdd(&g_t, (unsigned long long)tp);
    }
}

__global__ void finalize(float* out) {
    out[0] = (float)((double)g_c / (double)g_t);
}

extern "C" void kernel_launch(void* const* d_in, const int* in_sizes, int n_in,
                              void* d_out, int out_size) {
    const float* y  = (const float*)d_in[0];
    const float* yh = (const float*)d_in[1];
    const int*   st = (const int*)d_in[2];
    float* out = (float*)d_out;

    const int N = in_sizes[0];
    const int T = (N + TILE - 1) / TILE;
    const int nblk = T * (T + 1) / 2;

    init_counters<<<1, 1>>>();
    pair_kernel<<<nblk, 128>>>(y, yh, st, N);
    finalize<<<1, 1>>>(out);
}

// round 2
// speedup vs baseline: 1.0027x; 1.0027x over previous
#include <cuda_runtime.h>
#include <math.h>

#define TILE 128

// Global accumulators (no device allocation allowed; __device__ globals are the
// sanctioned scratch). Zeroed by init_counters at the start of every launch so
// the kernel_launch sequence is graph-replay deterministic.
__device__ unsigned long long g_c;
__device__ unsigned long long g_t;

__global__ void init_counters() {
    g_c = 0ull;
    g_t = 0ull;
}

// One block handles one 128x128 tile of the strict upper triangle (pairs i<j).
// blockIdx.x is decoded to (ti, tj) with ti <= tj. Thread t owns row
// i = ti*TILE + t and iterates over the j-tile held in shared memory
// (broadcast reads — conflict-free).
__global__ void __launch_bounds__(128)
pair_kernel(const float* __restrict__ y,
            const float* __restrict__ yh,
            const int*   __restrict__ st,
            int N)
{
    // ---- triangular decode: find r with r(r+1)/2 <= k < (r+1)(r+2)/2 ----
    const int k = blockIdx.x;
    int r = (int)((sqrtf(8.0f * (float)k + 1.0f) - 1.0f) * 0.5f);
    while ((r * (r + 1)) / 2 > k) --r;
    while (((r + 1) * (r + 2)) / 2 <= k) ++r;
    const int ti = k - (r * (r + 1)) / 2;  // column index  (<= r)
    const int tj = r;                      // row index: ti <= tj

    __shared__ float sy[TILE];
    __shared__ float syh[TILE];
    __shared__ int   ss[TILE];

    const int t = threadIdx.x;

    // Load the j-tile (coalesced). Out-of-range -> NaN so every comparison is
    // false and the padded element contributes 0 to both counters.
    {
        const int jg = tj * TILE + t;
        if (jg < N) {
            sy[t]  = y[jg];
            syh[t] = yh[jg];
            ss[t]  = (st[jg] == 1);
        } else {
            sy[t]  = __int_as_float(0x7fc00000);  // NaN
            syh[t] = __int_as_float(0x7fc00000);
            ss[t]  = 0;
        }
    }
    __syncthreads();

    // Per-thread i data.
    float yi, yhi;
    int si;
    {
        const int ig = ti * TILE + t;
        if (ig < N) {
            yi  = y[ig];
            yhi = yh[ig];
            si  = (st[ig] == 1);
        } else {
            yi  = __int_as_float(0x7fc00000);
            yhi = __int_as_float(0x7fc00000);
            si  = 0;
        }
    }

    unsigned int cc = 0, tp = 0;

    if (ti == tj) {
        // Diagonal tile: only local pairs j > i.
        for (int j = t + 1; j < TILE; ++j) {
            const float yj = sy[j], yhj = syh[j];
            const int sj = ss[j];
            const int ge  = (yi  >= yj);
            const int le  = (yi  <= yj);
            const int geh = (yhi >= yhj);
            const int leh = (yhi <= yhj);
            cc += (ge & geh & sj) | (le & leh & si);
            tp += (le & si) | (ge & sj);
        }
    } else {
        // Off-diagonal tile: every (i in ti-tile, j in tj-tile) has i < j.
        #pragma unroll 16
        for (int j = 0; j < TILE; ++j) {
            const float yj = sy[j], yhj = syh[j];
            const int sj = ss[j];
            const int ge  = (yi  >= yj);
            const int le  = (yi  <= yj);
            const int geh = (yhi >= yhj);
            const int leh = (yhi <= yhj);
            cc += (ge & geh & sj) | (le & leh & si);
            tp += (le & si) | (ge & sj);
        }
    }

    // Warp reduce, then one pair of atomics per warp.
    #pragma unroll
    for (int o = 16; o > 0; o >>= 1) {
        cc += __shfl_down_sync(0xffffffffu, cc, o);
        tp += __shfl_down_sync(0xffffffffu, tp, o);
    }
    if ((t & 31) == 0) {
        atomicAdd(&g_c, (unsigned long long)cc);
        atomicAdd(&g_t, (unsigned long long)tp);
    }
}

__global__ void finalize(float* out) {
    out[0] = (float)((double)g_c / (double)g_t);
}

extern "C" void kernel_launch(void* const* d_in, const int* in_sizes, int n_in,
                              void* d_out, int out_size) {
    const float* y  = (const float*)d_in[0];
    const float* yh = (const float*)d_in[1];
    const int*   st = (const int*)d_in[2];
    float* out = (float*)d_out;

    const int N = in_sizes[0];
    const int T = (N + TILE - 1) / TILE;
    const int nblk = T * (T + 1) / 2;

    init_counters<<<1, 1>>>();
    pair_kernel<<<nblk, 128>>>(y, yh, st, N);
    finalize<<<1, 1>>>(out);
}

// round 3
// speedup vs baseline: 2.2542x; 2.2482x over previous
#include <cuda_runtime.h>
#include <math.h>

#define NMAX 16384
#define TILE 128
#define HSZ  32768
#define NANF __int_as_float(0x7fc00000)

// ---------------- device scratch (no allocations allowed) ----------------
__device__ float d_py[NMAX];    // permuted y   (status-1 first, NaN padded)
__device__ float d_pyh[NMAX];   // permuted y_hat
__device__ int   d_M;           // number of status-1 items
__device__ unsigned long long d_ccA;    // sum over 1-1 pairs of ge&geh
__device__ unsigned long long d_ccLE;   // sum of le&leh&si (all pairs)
__device__ unsigned long long d_cntLE;  // sum over 1-0 pairs of le
__device__ unsigned long long d_T2;     // 1-1 pairs with y AND yh tied
__device__ unsigned long long d_hkey[HSZ];
__device__ unsigned int       d_hcnt[HSZ];

// ---------------- K1: count M, clear scratch, scatter-permute -------------
__global__ void __launch_bounds__(1024)
setup_kernel(const float* __restrict__ y, const float* __restrict__ yh,
             const int* __restrict__ st, int N)
{
    const int t = threadIdx.x;
    __shared__ int red, c1, c0;

    if (t == 0) { d_ccA = 0; d_ccLE = 0; d_cntLE = 0; d_T2 = 0; red = 0; }
    // clear hash table
    for (int i = t; i < HSZ; i += 1024) {
        d_hkey[i] = ~0ull;
        d_hcnt[i] = 0u;
    }
    __syncthreads();

    // count status-1
    int cnt = 0;
    const int iters = (N + 1023) / 1024;
    for (int k = 0; k < iters; ++k) {
        int i = t + k * 1024;
        if (i < N) cnt += (st[i] == 1);
    }
    #pragma unroll
    for (int o = 16; o > 0; o >>= 1) cnt += __shfl_down_sync(0xffffffffu, cnt, o);
    if ((t & 31) == 0) atomicAdd(&red, cnt);
    __syncthreads();
    const int M = red;
    if (t == 0) { d_M = M; c1 = 0; c0 = M; }
    __syncthreads();

    // warp-aggregated scatter: status-1 -> [0,M), status-0 -> [M,N)
    const int lane = t & 31;
    const unsigned ltm = (1u << lane) - 1u;
    for (int k = 0; k < iters; ++k) {
        int i = t + k * 1024;
        bool valid = i < N;
        int s = valid ? (st[i] == 1) : 0;
        unsigned m1 = __ballot_sync(0xffffffffu, valid && s);
        unsigned m0 = __ballot_sync(0xffffffffu, valid && !s);
        int b1 = 0, b0 = 0;
        if (lane == 0) {
            b1 = atomicAdd(&c1, __popc(m1));
            b0 = atomicAdd(&c0, __popc(m0));
        }
        b1 = __shfl_sync(0xffffffffu, b1, 0);
        b0 = __shfl_sync(0xffffffffu, b0, 0);
        if (valid) {
            int pos = s ? (b1 + __popc(m1 & ltm)) : (b0 + __popc(m0 & ltm));
            d_py[pos]  = y[i];
            d_pyh[pos] = yh[i];
        }
    }
    // NaN-pad tail (kills all comparisons for padded slots)
    for (int i = N + t; i < NMAX; i += 1024) {
        d_py[i]  = NANF;
        d_pyh[i] = NANF;
    }
}

// ------- K2: exact tie count T2 = #{i<j: s_i=s_j=1, y_i==y_j, yh_i==yh_j} -------
__global__ void tie_kernel(const float* __restrict__ y, const float* __restrict__ yh,
                           const int* __restrict__ st, int N)
{
    int i = blockIdx.x * blockDim.x + threadIdx.x;
    if (i >= N || st[i] != 1) return;
    float a = y[i];  if (a == 0.0f) a = 0.0f;   // canonicalize -0 -> +0
    float b = yh[i]; if (b == 0.0f) b = 0.0f;
    unsigned long long key = (unsigned long long)__float_as_uint(a)
                           | ((unsigned long long)__float_as_uint(b) << 32);
    if (key == ~0ull) key = ~1ull;  // avoid sentinel
    unsigned long long h = key;
    h ^= h >> 30; h *= 0xbf58476d1ce4e5b9ull;
    h ^= h >> 27; h *= 0x94d049bb133111ebull;
    h ^= h >> 31;
    int slot = (int)(h & (HSZ - 1));
    while (true) {
        unsigned long long prev = atomicCAS(&d_hkey[slot], ~0ull, key);
        if (prev == ~0ull || prev == key) {
            unsigned c = atomicAdd(&d_hcnt[slot], 1u);
            if (c) atomicAdd(&d_T2, (unsigned long long)c);
            break;
        }
        slot = (slot + 1) & (HSZ - 1);
    }
}

// ---------------- K3: tiled pair kernel over the i<j triangle --------------
__global__ void __launch_bounds__(128)
pair_kernel(int N)
{
    // triangular decode of blockIdx -> (ti, tj), ti <= tj
    const int k = blockIdx.x;
    int r = (int)((sqrtf(8.0f * (float)k + 1.0f) - 1.0f) * 0.5f);
    while ((r * (r + 1)) / 2 > k) --r;
    while (((r + 1) * (r + 2)) / 2 <= k) ++r;
    const int ti = k - (r * (r + 1)) / 2;
    const int tj = r;

    const int M = d_M;
    const int iBeg = ti * TILE, jBeg = tj * TILE;
    if (iBeg >= M) return;                       // (0,*) rows: no contribution
    const bool tjZero = (jBeg >= M);
    const bool tjOne  = (jBeg + TILE) <= M;

    __shared__ float2 s2[TILE];
    const int t = threadIdx.x;
    {
        const int jg = jBeg + t;
        s2[t] = make_float2(d_py[jg], d_pyh[jg]);   // padded with NaN already
    }
    __syncthreads();

    const int ig = iBeg + t;
    float yi  = d_py[ig];
    float yhi = d_pyh[ig];

    unsigned int ccA = 0, ccLE = 0, cntLE = 0;

    if (tjZero) {
        // 1-0 region: tp needs le; cc needs le&leh. Gate si by NaN poisoning.
        if (ig >= M) yi = NANF;
        #pragma unroll 32
        for (int j = 0; j < TILE; ++j) {
            float2 v = s2[j];
            asm("{\n\t"
                ".reg .pred p1, p2;\n\t"
                "setp.le.f32 p1, %2, %4;\n\t"
                "setp.le.and.f32 p2, %3, %5, p1;\n\t"
                "@p1 add.u32 %0, %0, 1;\n\t"
                "@p2 add.u32 %1, %1, 1;\n\t"
                "}"
                : "+r"(cntLE), "+r"(ccLE)
                : "f"(yi), "f"(yhi), "f"(v.x), "f"(v.y));
        }
    } else if (tjOne) {
        // 1-1 region: tp is analytic; only cc concordance terms needed.
        if (ti == tj) {
            for (int j = t + 1; j < TILE; ++j) {
                float2 v = s2[j];
                asm("{\n\t"
                    ".reg .pred p1, p2;\n\t"
                    "setp.ge.f32 p1, %2, %4;\n\t"
                    "setp.ge.and.f32 p1, %3, %5, p1;\n\t"
                    "setp.le.f32 p2, %2, %4;\n\t"
                    "setp.le.and.f32 p2, %3, %5, p2;\n\t"
                    "@p1 add.u32 %0, %0, 1;\n\t"
                    "@p2 add.u32 %1, %1, 1;\n\t"
                    "}"
                    : "+r"(ccA), "+r"(ccLE)
                    : "f"(yi), "f"(yhi), "f"(v.x), "f"(v.y));
            }
        } else {
            #pragma unroll 32
            for (int j = 0; j < TILE; ++j) {
                float2 v = s2[j];
                asm("{\n\t"
                    ".reg .pred p1, p2;\n\t"
                    "setp.ge.f32 p1, %2, %4;\n\t"
                    "setp.ge.and.f32 p1, %3, %5, p1;\n\t"
                    "setp.le.f32 p2, %2, %4;\n\t"
                    "setp.le.and.f32 p2, %3, %5, p2;\n\t"
                    "@p1 add.u32 %0, %0, 1;\n\t"
                    "@p2 add.u32 %1, %1, 1;\n\t"
                    "}"
                    : "+r"(ccA), "+r"(ccLE)
                    : "f"(yi), "f"(yhi), "f"(v.x), "f"(v.y));
            }
        }
    } else {
        // mixed boundary tile (tiny volume): general exact formula
        const int si = (ig < M);
        const int lim0 = (ti == tj) ? t + 1 : 0;
        for (int j = lim0; j < TILE; ++j) {
            float2 v = s2[j];
            const int sj  = (jBeg + j) < M;
            const int ge  = (yi  >= v.x);
            const int le  = (yi  <= v.x);
            const int geh = (yhi >= v.y);
            const int leh = (yhi <= v.y);
            ccA   += (ge & geh) & sj;
            ccLE  += (le & leh) & si;
            cntLE += (le & si) & (sj ^ 1);
        }
    }

    // block reduce: pack ccA|cntLE into u64, ccLE separate
    unsigned long long pk = (unsigned long long)ccA
                          | ((unsigned long long)cntLE << 32);
    unsigned int cl = ccLE;
    #pragma unroll
    for (int o = 16; o > 0; o >>= 1) {
        pk += __shfl_down_sync(0xffffffffu, pk, o);
        cl += __shfl_down_sync(0xffffffffu, cl, o);
    }
    __shared__ unsigned long long sp[4];
    __shared__ unsigned int       sc[4];
    const int wid = t >> 5;
    if ((t & 31) == 0) { sp[wid] = pk; sc[wid] = cl; }
    __syncthreads();
    if (t == 0) {
        unsigned long long P = sp[0] + sp[1] + sp[2] + sp[3];
        unsigned long long C = (unsigned long long)(sc[0] + sc[1] + sc[2] + sc[3]);
        atomicAdd(&d_ccA,   P & 0xffffffffull);
        atomicAdd(&d_cntLE, P >> 32);
        atomicAdd(&d_ccLE,  C);
    }
}

// ---------------- K4: finalize -------------------------------------------
__global__ void finalize(float* out)
{
    unsigned long long c = d_ccA + d_ccLE - d_T2;
    unsigned long long M = (unsigned long long)d_M;
    unsigned long long tot = M * (M - 1) / 2 + d_cntLE;
    out[0] = (float)(long long)c / (float)(long long)tot;
}

// ---------------- launch ---------------------------------------------------
extern "C" void kernel_launch(void* const* d_in, const int* in_sizes, int n_in,
                              void* d_out, int out_size)
{
    const float* y  = (const float*)d_in[0];
    const float* yh = (const float*)d_in[1];
    const int*   st = (const int*)d_in[2];
    float* out = (float*)d_out;

    const int N = in_sizes[0];
    const int T = (N + TILE - 1) / TILE;
    const int nblk = T * (T + 1) / 2;

    setup_kernel<<<1, 1024>>>(y, yh, st, N);
    tie_kernel<<<(N + 255) / 256, 256>>>(y, yh, st, N);
    pair_kernel<<<nblk, 128>>>(N);
    finalize<<<1, 1>>>(out);
}